// round 15
// baseline (speedup 1.0000x reference)
#include <cuda_runtime.h>
#include <cuda_bf16.h>
#include <cstdint>

#define N_NODES 50000
#define N_EDGES 600000
#define DIM 128
#define CAP 64
#define OVMAX 8192

// Device scratch (zero-init at load; invariants restored each call)
__device__ float g_deg[N_NODES];                    // reset in k_dinv
__device__ float g_dinv[N_NODES];
__device__ float g_y[(size_t)N_NODES * DIM];        // y = x @ W^T
__device__ int   g_cnt[N_NODES];                    // reset in k_aggregate
__device__ int2  g_ebuck[(size_t)N_NODES * CAP];
__device__ int   g_ovcnt;
__device__ int   g_ovuse;
__device__ int   g_ovt[OVMAX];
__device__ int2  g_ovsw[OVMAX];
// W pre-packed in m16n8k16 b-fragment order: [chunk 8][ntile 16][lane 32]
__device__ uint2 g_WfH[8 * 16 * 32];
__device__ uint2 g_WfL[8 * 16 * 32];

__device__ __forceinline__ void mma16816bf(float& c0, float& c1, float& c2, float& c3,
                                           uint32_t a0, uint32_t a1, uint32_t a2, uint32_t a3,
                                           uint32_t b0, uint32_t b1) {
    asm volatile("mma.sync.aligned.m16n8k16.row.col.f32.bf16.bf16.f32 "
                 "{%0,%1,%2,%3}, {%4,%5,%6,%7}, {%8,%9}, {%0,%1,%2,%3};"
                 : "+f"(c0), "+f"(c1), "+f"(c2), "+f"(c3)
                 : "r"(a0), "r"(a1), "r"(a2), "r"(a3), "r"(b0), "r"(b1));
}

__device__ __forceinline__ uint32_t pkh(float a, float b, float& ra, float& rb) {
    __nv_bfloat16 ha = __float2bfloat16(a);
    __nv_bfloat16 hb = __float2bfloat16(b);
    ra = a - __bfloat162float(ha);
    rb = b - __bfloat162float(hb);
    __nv_bfloat162 h2(ha, hb);
    return *(uint32_t*)&h2;
}
__device__ __forceinline__ uint32_t pk0(float a, float b) {
    __nv_bfloat162 h2(__float2bfloat16(a), __float2bfloat16(b));
    return *(uint32_t*)&h2;
}

// ---------------- prep: pack W into b-fragment order ----------------------
__global__ void k_prepW(const float* __restrict__ W) {
    int i = blockIdx.x * blockDim.x + threadIdx.x;   // 0..4095
    if (i >= 8 * 16 * 32) return;
    int l  = i & 31;
    int nt = (i >> 5) & 15;
    int c  = i >> 9;
    int n  = nt * 8 + (l >> 2);
    int k0 = c * 16 + (l & 3) * 2;
    const float* wr = W + (size_t)n * DIM;
    float r0, r1, r2, r3;
    uint32_t h0 = pkh(wr[k0], wr[k0 + 1], r0, r1);
    uint32_t h1 = pkh(wr[k0 + 8], wr[k0 + 9], r2, r3);
    g_WfH[i] = make_uint2(h0, h1);
    g_WfL[i] = make_uint2(pk0(r0, r1), pk0(r2, r3));
}

// =====================================================================
// Fused kernel: blocks [0,EB) = edge pass; blocks [EB,EB+GB) = GEMM tile.
// GEMM is SMEM-FREE: A direct-gathered in fragment layout, B from
// pre-packed L1-resident fragment arrays, 3-term bf16 split.
// =====================================================================
__global__ __launch_bounds__(256, 2) void k_fused(const float* __restrict__ x,
                                                  const void* __restrict__ ei,
                                                  const float* __restrict__ ew,
                                                  int M, int E, int GB, int EB) {
    int bid = blockIdx.x;
    if (bid >= EB) {
        // ---------------- GEMM tile ----------------
        int tid = threadIdx.x;
        int lane = tid & 31;
        int wrp = tid >> 5;
        int wm = wrp & 3;
        int wn = wrp >> 2;
        int rowBase = (bid - EB) * 128;

        int g  = lane >> 2;
        int tg = lane & 3;

        float acc[2][8][4];
        #pragma unroll
        for (int mt = 0; mt < 2; mt++)
            #pragma unroll
            for (int nt = 0; nt < 8; nt++)
                #pragma unroll
                for (int c = 0; c < 4; c++) acc[mt][nt][c] = 0.0f;

        int m1g[2], m2g[2];
        bool v1[2], v2[2];
        #pragma unroll
        for (int mt = 0; mt < 2; mt++) {
            int m1 = rowBase + wm * 32 + mt * 16 + g;
            m1g[mt] = m1; m2g[mt] = m1 + 8;
            v1[mt] = (m1 < M); v2[mt] = (m1 + 8 < M);
        }

        #pragma unroll
        for (int c = 0; c < 8; c++) {
            int k0 = c * 16 + tg * 2;
            uint2 bh[8], bl[8];
            #pragma unroll
            for (int nt = 0; nt < 8; nt++) {
                int idx = ((c * 16 + wn * 8 + nt) << 5) + lane;
                bh[nt] = g_WfH[idx];
                bl[nt] = g_WfL[idx];
            }
            uint32_t ah[2][4], al[2][4];
            #pragma unroll
            for (int mt = 0; mt < 2; mt++) {
                float2 x00 = v1[mt] ? *(const float2*)(x + (size_t)m1g[mt] * DIM + k0)     : make_float2(0.f, 0.f);
                float2 x10 = v2[mt] ? *(const float2*)(x + (size_t)m2g[mt] * DIM + k0)     : make_float2(0.f, 0.f);
                float2 x01 = v1[mt] ? *(const float2*)(x + (size_t)m1g[mt] * DIM + k0 + 8) : make_float2(0.f, 0.f);
                float2 x11 = v2[mt] ? *(const float2*)(x + (size_t)m2g[mt] * DIM + k0 + 8) : make_float2(0.f, 0.f);
                float r0, r1;
                ah[mt][0] = pkh(x00.x, x00.y, r0, r1); al[mt][0] = pk0(r0, r1);
                ah[mt][1] = pkh(x10.x, x10.y, r0, r1); al[mt][1] = pk0(r0, r1);
                ah[mt][2] = pkh(x01.x, x01.y, r0, r1); al[mt][2] = pk0(r0, r1);
                ah[mt][3] = pkh(x11.x, x11.y, r0, r1); al[mt][3] = pk0(r0, r1);
            }
            #pragma unroll
            for (int nt = 0; nt < 8; nt++) {
                #pragma unroll
                for (int mt = 0; mt < 2; mt++) {
                    float* cc = acc[mt][nt];
                    mma16816bf(cc[0], cc[1], cc[2], cc[3],
                               ah[mt][0], ah[mt][1], ah[mt][2], ah[mt][3],
                               bh[nt].x, bh[nt].y);
                    mma16816bf(cc[0], cc[1], cc[2], cc[3],
                               ah[mt][0], ah[mt][1], ah[mt][2], ah[mt][3],
                               bl[nt].x, bl[nt].y);
                    mma16816bf(cc[0], cc[1], cc[2], cc[3],
                               al[mt][0], al[mt][1], al[mt][2], al[mt][3],
                               bh[nt].x, bh[nt].y);
                }
            }
        }

        #pragma unroll
        for (int mt = 0; mt < 2; mt++) {
            #pragma unroll
            for (int nt = 0; nt < 8; nt++) {
                int col = wn * 64 + nt * 8 + 2 * tg;
                float* cc = acc[mt][nt];
                if (v1[mt])
                    *(float2*)(g_y + (size_t)m1g[mt] * DIM + col) = make_float2(cc[0], cc[1]);
                if (v2[mt])
                    *(float2*)(g_y + (size_t)m2g[mt] * DIM + col) = make_float2(cc[2], cc[3]);
            }
        }
    } else {
        // ---------------- edge block ----------------
        int b = bid;
        int chunk = (E + EB - 1) / EB;
        int beg = b * chunk;
        int end = beg + chunk; if (end > E) end = E;
        if (beg >= end) return;

        __shared__ int s_is64;
        if (threadIdx.x == 0) s_is64 = 1;
        __syncthreads();
        const long long* p64 = (const long long*)ei;
        const int*       p32 = (const int*)ei;
        int samp = end - beg; if (samp > 256) samp = 256;
        if ((int)threadIdx.x < samp) {
            long long v = p64[beg + threadIdx.x];
            if (v < 0 || v >= (long long)N_NODES) s_is64 = 0;
        }
        __syncthreads();
        int is64 = s_is64;

        for (int i = beg + threadIdx.x; i < end; i += 256) {
            int s, t;
            float w = ew[i];
            if (is64) { s = (int)p64[i]; t = (int)p64[(size_t)E + i]; }
            else      { s = p32[i];      t = p32[(size_t)E + i]; }
            atomicAdd(&g_deg[s], w);
            int pos = atomicAdd(&g_cnt[t], 1);
            if (pos < CAP) {
                g_ebuck[(size_t)t * CAP + pos] = make_int2(s, __float_as_int(w));
            } else {
                int o = atomicAdd(&g_ovcnt, 1);
                if (o < OVMAX) { g_ovt[o] = t; g_ovsw[o] = make_int2(s, __float_as_int(w)); }
            }
        }
    }
}

// ---------------- dinv = rsqrt(deg + 1); reset deg; latch overflow --------
__global__ void k_dinv(int n) {
    int i = blockIdx.x * blockDim.x + threadIdx.x;
    if (i < n) {
        g_dinv[i] = rsqrtf(g_deg[i] + 1.0f);
        g_deg[i] = 0.0f;
    }
    if (i == 0) {
        int c = g_ovcnt;
        g_ovuse = (c < OVMAX) ? c : OVMAX;
        g_ovcnt = 0;
    }
}

// ---------------- pull-aggregation: warp per node ------------------------
// Meta strip holds (row_byte_offset, wn) so the main loop is pure
// LDS.64 -> LDG.128 -> 4xFFMA with zero 64-bit address math.
// 8-wide gather batching (meta from 2-cycle LDS) -> MLP ~8.
__global__ __launch_bounds__(256) void k_aggregate(const float* __restrict__ bias,
                                                   float* __restrict__ out, int n) {
    __shared__ float2 s_meta[8][CAP];
    int wip  = threadIdx.x >> 5;
    int warp = (blockIdx.x * blockDim.x + threadIdx.x) >> 5;
    int lane = threadIdx.x & 31;
    if (warp >= n) return;
    int t = warp;

    int cnt = g_cnt[t];
    if (cnt > CAP) cnt = CAP;
    const int2* buck = g_ebuck + (size_t)t * CAP;
    float di = g_dinv[t];

    // per-thread base: y + lane's float4 slot (folds lane*16 into the pointer)
    const char* ybase = (const char*)g_y + (size_t)lane * 16;

    // preload + normalize metadata; store row BYTE offset (src * 512)
    for (int p = lane; p < cnt; p += 32) {
        int2 e = buck[p];
        float wn = __int_as_float(e.y) * g_dinv[e.x] * di;
        s_meta[wip][p] = make_float2(__int_as_float(e.x << 9), wn);
    }
    __syncwarp();

    float sc = di * di;
    const float4* y4 = (const float4*)g_y;
    float4 self = y4[(size_t)t * 32 + lane];
    float4 bi = ((const float4*)bias)[lane];
    float4 a0, a1, a2, a3;
    a0.x = self.x * sc + bi.x;
    a0.y = self.y * sc + bi.y;
    a0.z = self.z * sc + bi.z;
    a0.w = self.w * sc + bi.w;
    a1 = make_float4(0.f, 0.f, 0.f, 0.f);
    a2 = make_float4(0.f, 0.f, 0.f, 0.f);
    a3 = make_float4(0.f, 0.f, 0.f, 0.f);

    int j = 0;
    for (; j + 8 <= cnt; j += 8) {
        float2 m[8];
        #pragma unroll
        for (int q = 0; q < 8; q++) m[q] = s_meta[wip][j + q];
        float4 v[8];
        #pragma unroll
        for (int q = 0; q < 8; q++)
            v[q] = *(const float4*)(ybase + (uint32_t)__float_as_int(m[q].x));
        #pragma unroll
        for (int q = 0; q < 8; q += 4) {
            float w0 = m[q].y, w1 = m[q + 1].y, w2 = m[q + 2].y, w3 = m[q + 3].y;
            a0.x += v[q].x * w0;     a0.y += v[q].y * w0;     a0.z += v[q].z * w0;     a0.w += v[q].w * w0;
            a1.x += v[q + 1].x * w1; a1.y += v[q + 1].y * w1; a1.z += v[q + 1].z * w1; a1.w += v[q + 1].w * w1;
            a2.x += v[q + 2].x * w2; a2.y += v[q + 2].y * w2; a2.z += v[q + 2].z * w2; a2.w += v[q + 2].w * w2;
            a3.x += v[q + 3].x * w3; a3.y += v[q + 3].y * w3; a3.z += v[q + 3].z * w3; a3.w += v[q + 3].w * w3;
        }
    }
    for (; j < cnt; j++) {
        float2 m = s_meta[wip][j];
        float4 v = *(const float4*)(ybase + (uint32_t)__float_as_int(m.x));
        a0.x += v.x * m.y; a0.y += v.y * m.y; a0.z += v.z * m.y; a0.w += v.w * m.y;
    }

    // overflow tail (normally empty)
    int ov = g_ovuse;
    for (int i = 0; i < ov; i++) {
        if (g_ovt[i] == t) {
            int2 e = g_ovsw[i];
            float wn = __int_as_float(e.y) * g_dinv[e.x] * di;
            float4 v = y4[(size_t)e.x * 32 + lane];
            a0.x += v.x * wn; a0.y += v.y * wn; a0.z += v.z * wn; a0.w += v.w * wn;
        }
    }

    float4 res;
    res.x = (a0.x + a1.x) + (a2.x + a3.x);
    res.y = (a0.y + a1.y) + (a2.y + a3.y);
    res.z = (a0.z + a1.z) + (a2.z + a3.z);
    res.w = (a0.w + a1.w) + (a2.w + a3.w);
    ((float4*)out)[(size_t)t * 32 + lane] = res;
    if (lane == 0) g_cnt[t] = 0;
}

extern "C" void kernel_launch(void* const* d_in, const int* in_sizes, int n_in,
                              void* d_out, int out_size) {
    const float* x  = (const float*)d_in[0];
    const void*  ei = d_in[1];
    const float* ew = (const float*)d_in[2];
    const float* W  = (const float*)d_in[3];
    const float* b  = (const float*)d_in[4];
    float* out = (float*)d_out;

    int N = in_sizes[0] / DIM;
    int E = in_sizes[1] / 2;

    int GB = (N + 127) / 128;
    int EB = 296;

    k_prepW<<<16, 256>>>(W);
    k_fused<<<GB + EB, 256>>>(x, ei, ew, N, E, GB, EB);
    k_dinv<<<(N + 255) / 256, 256>>>(N);
    k_aggregate<<<(N * 32 + 255) / 256, 256>>>(b, out, N);
}

// round 16
// speedup vs baseline: 1.0519x; 1.0519x over previous
#include <cuda_runtime.h>
#include <cuda_bf16.h>
#include <cstdint>

#define N_NODES 50000
#define N_EDGES 600000
#define DIM 128
#define CAP 64
#define OVMAX 8192

// Device scratch (zero-init at load; invariants restored each call)
__device__ float g_deg[N_NODES];                    // reset in k_dinv
__device__ float g_dinv[N_NODES];
__device__ float g_y[(size_t)N_NODES * DIM];        // y = x @ W^T
__device__ int   g_cnt[N_NODES];                    // reset in k_aggregate
__device__ int2  g_ebuck[(size_t)N_NODES * CAP];
__device__ int   g_ovcnt;
__device__ int   g_ovuse;
__device__ int   g_ovt[OVMAX];
__device__ int2  g_ovsw[OVMAX];
// W pre-packed in m16n8k16 b-fragment order: [chunk 8][ntile 16][lane 32]
__device__ uint2 g_WfH[8 * 16 * 32];
__device__ uint2 g_WfL[8 * 16 * 32];

__device__ __forceinline__ void mma16816bf(float& c0, float& c1, float& c2, float& c3,
                                           uint32_t a0, uint32_t a1, uint32_t a2, uint32_t a3,
                                           uint32_t b0, uint32_t b1) {
    asm volatile("mma.sync.aligned.m16n8k16.row.col.f32.bf16.bf16.f32 "
                 "{%0,%1,%2,%3}, {%4,%5,%6,%7}, {%8,%9}, {%0,%1,%2,%3};"
                 : "+f"(c0), "+f"(c1), "+f"(c2), "+f"(c3)
                 : "r"(a0), "r"(a1), "r"(a2), "r"(a3), "r"(b0), "r"(b1));
}

__device__ __forceinline__ uint32_t pkh(float a, float b, float& ra, float& rb) {
    __nv_bfloat16 ha = __float2bfloat16(a);
    __nv_bfloat16 hb = __float2bfloat16(b);
    ra = a - __bfloat162float(ha);
    rb = b - __bfloat162float(hb);
    __nv_bfloat162 h2(ha, hb);
    return *(uint32_t*)&h2;
}
__device__ __forceinline__ uint32_t pk0(float a, float b) {
    __nv_bfloat162 h2(__float2bfloat16(a), __float2bfloat16(b));
    return *(uint32_t*)&h2;
}

// ---------------- prep: pack W into b-fragment order ----------------------
__global__ void k_prepW(const float* __restrict__ W) {
    int i = blockIdx.x * blockDim.x + threadIdx.x;   // 0..4095
    if (i >= 8 * 16 * 32) return;
    int l  = i & 31;
    int nt = (i >> 5) & 15;
    int c  = i >> 9;
    int n  = nt * 8 + (l >> 2);
    int k0 = c * 16 + (l & 3) * 2;
    const float* wr = W + (size_t)n * DIM;
    float r0, r1, r2, r3;
    uint32_t h0 = pkh(wr[k0], wr[k0 + 1], r0, r1);
    uint32_t h1 = pkh(wr[k0 + 8], wr[k0 + 9], r2, r3);
    g_WfH[i] = make_uint2(h0, h1);
    g_WfL[i] = make_uint2(pk0(r0, r1), pk0(r2, r3));
}

// =====================================================================
// Fused kernel: blocks [0,EB) = edge pass; blocks [EB,EB+GB) = GEMM tile.
// GEMM is SMEM-FREE: A direct-gathered in fragment layout, B from
// pre-packed L1-resident fragment arrays, 3-term bf16 split.
// =====================================================================
__global__ __launch_bounds__(256, 2) void k_fused(const float* __restrict__ x,
                                                  const void* __restrict__ ei,
                                                  const float* __restrict__ ew,
                                                  int M, int E, int GB, int EB) {
    int bid = blockIdx.x;
    if (bid >= EB) {
        // ---------------- GEMM tile ----------------
        int tid = threadIdx.x;
        int lane = tid & 31;
        int wrp = tid >> 5;
        int wm = wrp & 3;
        int wn = wrp >> 2;
        int rowBase = (bid - EB) * 128;

        int g  = lane >> 2;
        int tg = lane & 3;

        float acc[2][8][4];
        #pragma unroll
        for (int mt = 0; mt < 2; mt++)
            #pragma unroll
            for (int nt = 0; nt < 8; nt++)
                #pragma unroll
                for (int c = 0; c < 4; c++) acc[mt][nt][c] = 0.0f;

        int m1g[2], m2g[2];
        bool v1[2], v2[2];
        #pragma unroll
        for (int mt = 0; mt < 2; mt++) {
            int m1 = rowBase + wm * 32 + mt * 16 + g;
            m1g[mt] = m1; m2g[mt] = m1 + 8;
            v1[mt] = (m1 < M); v2[mt] = (m1 + 8 < M);
        }

        #pragma unroll
        for (int c = 0; c < 8; c++) {
            int k0 = c * 16 + tg * 2;
            uint2 bh[8], bl[8];
            #pragma unroll
            for (int nt = 0; nt < 8; nt++) {
                int idx = ((c * 16 + wn * 8 + nt) << 5) + lane;
                bh[nt] = g_WfH[idx];
                bl[nt] = g_WfL[idx];
            }
            uint32_t ah[2][4], al[2][4];
            #pragma unroll
            for (int mt = 0; mt < 2; mt++) {
                float2 x00 = v1[mt] ? *(const float2*)(x + (size_t)m1g[mt] * DIM + k0)     : make_float2(0.f, 0.f);
                float2 x10 = v2[mt] ? *(const float2*)(x + (size_t)m2g[mt] * DIM + k0)     : make_float2(0.f, 0.f);
                float2 x01 = v1[mt] ? *(const float2*)(x + (size_t)m1g[mt] * DIM + k0 + 8) : make_float2(0.f, 0.f);
                float2 x11 = v2[mt] ? *(const float2*)(x + (size_t)m2g[mt] * DIM + k0 + 8) : make_float2(0.f, 0.f);
                float r0, r1;
                ah[mt][0] = pkh(x00.x, x00.y, r0, r1); al[mt][0] = pk0(r0, r1);
                ah[mt][1] = pkh(x10.x, x10.y, r0, r1); al[mt][1] = pk0(r0, r1);
                ah[mt][2] = pkh(x01.x, x01.y, r0, r1); al[mt][2] = pk0(r0, r1);
                ah[mt][3] = pkh(x11.x, x11.y, r0, r1); al[mt][3] = pk0(r0, r1);
            }
            #pragma unroll
            for (int nt = 0; nt < 8; nt++) {
                #pragma unroll
                for (int mt = 0; mt < 2; mt++) {
                    float* cc = acc[mt][nt];
                    mma16816bf(cc[0], cc[1], cc[2], cc[3],
                               ah[mt][0], ah[mt][1], ah[mt][2], ah[mt][3],
                               bh[nt].x, bh[nt].y);
                    mma16816bf(cc[0], cc[1], cc[2], cc[3],
                               ah[mt][0], ah[mt][1], ah[mt][2], ah[mt][3],
                               bl[nt].x, bl[nt].y);
                    mma16816bf(cc[0], cc[1], cc[2], cc[3],
                               al[mt][0], al[mt][1], al[mt][2], al[mt][3],
                               bh[nt].x, bh[nt].y);
                }
            }
        }

        #pragma unroll
        for (int mt = 0; mt < 2; mt++) {
            #pragma unroll
            for (int nt = 0; nt < 8; nt++) {
                int col = wn * 64 + nt * 8 + 2 * tg;
                float* cc = acc[mt][nt];
                if (v1[mt])
                    *(float2*)(g_y + (size_t)m1g[mt] * DIM + col) = make_float2(cc[0], cc[1]);
                if (v2[mt])
                    *(float2*)(g_y + (size_t)m2g[mt] * DIM + col) = make_float2(cc[2], cc[3]);
            }
        }
    } else {
        // ---------------- edge block ----------------
        int b = bid;
        int chunk = (E + EB - 1) / EB;
        int beg = b * chunk;
        int end = beg + chunk; if (end > E) end = E;
        if (beg >= end) return;

        __shared__ int s_is64;
        if (threadIdx.x == 0) s_is64 = 1;
        __syncthreads();
        const long long* p64 = (const long long*)ei;
        const int*       p32 = (const int*)ei;
        int samp = end - beg; if (samp > 256) samp = 256;
        if ((int)threadIdx.x < samp) {
            long long v = p64[beg + threadIdx.x];
            if (v < 0 || v >= (long long)N_NODES) s_is64 = 0;
        }
        __syncthreads();
        int is64 = s_is64;

        for (int i = beg + threadIdx.x; i < end; i += 256) {
            int s, t;
            float w = ew[i];
            if (is64) { s = (int)p64[i]; t = (int)p64[(size_t)E + i]; }
            else      { s = p32[i];      t = p32[(size_t)E + i]; }
            atomicAdd(&g_deg[s], w);
            int pos = atomicAdd(&g_cnt[t], 1);
            if (pos < CAP) {
                g_ebuck[(size_t)t * CAP + pos] = make_int2(s, __float_as_int(w));
            } else {
                int o = atomicAdd(&g_ovcnt, 1);
                if (o < OVMAX) { g_ovt[o] = t; g_ovsw[o] = make_int2(s, __float_as_int(w)); }
            }
        }
    }
}

// ---------------- dinv = rsqrt(deg + 1); reset deg; latch overflow --------
__global__ void k_dinv(int n) {
    int i = blockIdx.x * blockDim.x + threadIdx.x;
    if (i < n) {
        g_dinv[i] = rsqrtf(g_deg[i] + 1.0f);
        g_deg[i] = 0.0f;
    }
    if (i == 0) {
        int c = g_ovcnt;
        g_ovuse = (c < OVMAX) ? c : OVMAX;
        g_ovcnt = 0;
    }
}

// ---------------- pull-aggregation: warp per node (R14 form) --------------
// Lane-parallel metadata preload into per-warp smem strip; main loop is
// broadcast LDS + 4 batched independent row gathers. launch_bounds(256,6)
// caps regs to lift occupancy (latency-bound kernel).
__global__ __launch_bounds__(256, 6) void k_aggregate(const float* __restrict__ bias,
                                                      float* __restrict__ out, int n) {
    __shared__ float2 s_meta[8][CAP];
    int wip  = threadIdx.x >> 5;
    int warp = (blockIdx.x * blockDim.x + threadIdx.x) >> 5;
    int lane = threadIdx.x & 31;
    if (warp >= n) return;
    int t = warp;

    int cnt = g_cnt[t];
    if (cnt > CAP) cnt = CAP;
    const float4* y4 = (const float4*)g_y;
    const int2* buck = g_ebuck + (size_t)t * CAP;
    float di = g_dinv[t];

    // preload + normalize metadata (coalesced; one dinv gather per edge-lane)
    for (int p = lane; p < cnt; p += 32) {
        int2 e = buck[p];
        float wn = __int_as_float(e.y) * g_dinv[e.x] * di;
        s_meta[wip][p] = make_float2(__int_as_float(e.x), wn);
    }
    __syncwarp();

    float sc = di * di;
    float4 self = y4[(size_t)t * 32 + lane];
    float4 bi = ((const float4*)bias)[lane];
    float4 acc0, acc1;
    acc0.x = self.x * sc + bi.x;
    acc0.y = self.y * sc + bi.y;
    acc0.z = self.z * sc + bi.z;
    acc0.w = self.w * sc + bi.w;
    acc1 = make_float4(0.f, 0.f, 0.f, 0.f);

    int j = 0;
    for (; j + 4 <= cnt; j += 4) {
        float2 m0 = s_meta[wip][j];
        float2 m1 = s_meta[wip][j + 1];
        float2 m2 = s_meta[wip][j + 2];
        float2 m3 = s_meta[wip][j + 3];
        float4 v0 = y4[(size_t)__float_as_int(m0.x) * 32 + lane];
        float4 v1 = y4[(size_t)__float_as_int(m1.x) * 32 + lane];
        float4 v2 = y4[(size_t)__float_as_int(m2.x) * 32 + lane];
        float4 v3 = y4[(size_t)__float_as_int(m3.x) * 32 + lane];
        acc0.x += v0.x * m0.y; acc0.y += v0.y * m0.y; acc0.z += v0.z * m0.y; acc0.w += v0.w * m0.y;
        acc1.x += v1.x * m1.y; acc1.y += v1.y * m1.y; acc1.z += v1.z * m1.y; acc1.w += v1.w * m1.y;
        acc0.x += v2.x * m2.y; acc0.y += v2.y * m2.y; acc0.z += v2.z * m2.y; acc0.w += v2.w * m2.y;
        acc1.x += v3.x * m3.y; acc1.y += v3.y * m3.y; acc1.z += v3.z * m3.y; acc1.w += v3.w * m3.y;
    }
    for (; j < cnt; j++) {
        float2 m = s_meta[wip][j];
        float4 v = y4[(size_t)__float_as_int(m.x) * 32 + lane];
        acc0.x += v.x * m.y; acc0.y += v.y * m.y; acc0.z += v.z * m.y; acc0.w += v.w * m.y;
    }

    // overflow tail (normally empty)
    int ov = g_ovuse;
    for (int i = 0; i < ov; i++) {
        if (g_ovt[i] == t) {
            int2 e = g_ovsw[i];
            float wn = __int_as_float(e.y) * g_dinv[e.x] * di;
            float4 v = y4[(size_t)e.x * 32 + lane];
            acc0.x += v.x * wn; acc0.y += v.y * wn; acc0.z += v.z * wn; acc0.w += v.w * wn;
        }
    }

    float4 res;
    res.x = acc0.x + acc1.x;
    res.y = acc0.y + acc1.y;
    res.z = acc0.z + acc1.z;
    res.w = acc0.w + acc1.w;
    ((float4*)out)[(size_t)t * 32 + lane] = res;
    if (lane == 0) g_cnt[t] = 0;
}

extern "C" void kernel_launch(void* const* d_in, const int* in_sizes, int n_in,
                              void* d_out, int out_size) {
    const float* x  = (const float*)d_in[0];
    const void*  ei = d_in[1];
    const float* ew = (const float*)d_in[2];
    const float* W  = (const float*)d_in[3];
    const float* b  = (const float*)d_in[4];
    float* out = (float*)d_out;

    int N = in_sizes[0] / DIM;
    int E = in_sizes[1] / 2;

    int GB = (N + 127) / 128;
    int EB = 296;

    k_prepW<<<16, 256>>>(W);
    k_fused<<<GB + EB, 256>>>(x, ei, ew, N, E, GB, EB);
    k_dinv<<<(N + 255) / 256, 256>>>(N);
    k_aggregate<<<(N * 32 + 255) / 256, 256>>>(b, out, N);
}

// round 17
// speedup vs baseline: 1.1118x; 1.0570x over previous
#include <cuda_runtime.h>
#include <cuda_bf16.h>
#include <cstdint>

#define N_NODES 50000
#define N_EDGES 600000
#define DIM 128
#define CAP 64
#define OVMAX 8192

// Device scratch (zero-init at load; invariants restored each call)
__device__ float g_deg[N_NODES];                    // reset in k_dinv
__device__ float g_dinv[N_NODES];
__device__ float g_y[(size_t)N_NODES * DIM];        // y = x @ W^T
__device__ int   g_cnt[N_NODES];                    // reset in k_aggregate
__device__ int2  g_ebuck[(size_t)N_NODES * CAP];
__device__ int   g_ovcnt;
__device__ int   g_ovuse;
__device__ int   g_ovt[OVMAX];
__device__ int2  g_ovsw[OVMAX];
// W pre-packed in m16n8k16 b-fragment order: [chunk 8][ntile 16][lane 32]
__device__ uint2 g_WfH[8 * 16 * 32];
__device__ uint2 g_WfL[8 * 16 * 32];

__device__ __forceinline__ void mma16816bf(float& c0, float& c1, float& c2, float& c3,
                                           uint32_t a0, uint32_t a1, uint32_t a2, uint32_t a3,
                                           uint32_t b0, uint32_t b1) {
    asm volatile("mma.sync.aligned.m16n8k16.row.col.f32.bf16.bf16.f32 "
                 "{%0,%1,%2,%3}, {%4,%5,%6,%7}, {%8,%9}, {%0,%1,%2,%3};"
                 : "+f"(c0), "+f"(c1), "+f"(c2), "+f"(c3)
                 : "r"(a0), "r"(a1), "r"(a2), "r"(a3), "r"(b0), "r"(b1));
}

__device__ __forceinline__ uint32_t pkh(float a, float b, float& ra, float& rb) {
    __nv_bfloat16 ha = __float2bfloat16(a);
    __nv_bfloat16 hb = __float2bfloat16(b);
    ra = a - __bfloat162float(ha);
    rb = b - __bfloat162float(hb);
    __nv_bfloat162 h2(ha, hb);
    return *(uint32_t*)&h2;
}
__device__ __forceinline__ uint32_t pk0(float a, float b) {
    __nv_bfloat162 h2(__float2bfloat16(a), __float2bfloat16(b));
    return *(uint32_t*)&h2;
}

// ---------------- prep: pack W into b-fragment order ----------------------
__global__ void k_prepW(const float* __restrict__ W) {
    int i = blockIdx.x * blockDim.x + threadIdx.x;   // 0..4095
    if (i >= 8 * 16 * 32) return;
    int l  = i & 31;
    int nt = (i >> 5) & 15;
    int c  = i >> 9;
    int n  = nt * 8 + (l >> 2);
    int k0 = c * 16 + (l & 3) * 2;
    const float* wr = W + (size_t)n * DIM;
    float r0, r1, r2, r3;
    uint32_t h0 = pkh(wr[k0], wr[k0 + 1], r0, r1);
    uint32_t h1 = pkh(wr[k0 + 8], wr[k0 + 9], r2, r3);
    g_WfH[i] = make_uint2(h0, h1);
    g_WfL[i] = make_uint2(pk0(r0, r1), pk0(r2, r3));
}

// =====================================================================
// Fused kernel: blocks [0,EB) = edge pass; blocks [EB,EB+GB) = GEMM tile.
// EB chosen so grid = EB + GB = 592 = exactly 2 full waves (2 CTA/SM x 148).
// GEMM is SMEM-FREE: A direct-gathered in fragment layout, B from
// pre-packed L1-resident fragment arrays, 3-term bf16 split.
// =====================================================================
__global__ __launch_bounds__(256, 2) void k_fused(const float* __restrict__ x,
                                                  const void* __restrict__ ei,
                                                  const float* __restrict__ ew,
                                                  int M, int E, int GB, int EB) {
    int bid = blockIdx.x;
    if (bid >= EB) {
        // ---------------- GEMM tile ----------------
        int tid = threadIdx.x;
        int lane = tid & 31;
        int wrp = tid >> 5;
        int wm = wrp & 3;
        int wn = wrp >> 2;
        int rowBase = (bid - EB) * 128;

        int g  = lane >> 2;
        int tg = lane & 3;

        float acc[2][8][4];
        #pragma unroll
        for (int mt = 0; mt < 2; mt++)
            #pragma unroll
            for (int nt = 0; nt < 8; nt++)
                #pragma unroll
                for (int c = 0; c < 4; c++) acc[mt][nt][c] = 0.0f;

        int m1g[2], m2g[2];
        bool v1[2], v2[2];
        #pragma unroll
        for (int mt = 0; mt < 2; mt++) {
            int m1 = rowBase + wm * 32 + mt * 16 + g;
            m1g[mt] = m1; m2g[mt] = m1 + 8;
            v1[mt] = (m1 < M); v2[mt] = (m1 + 8 < M);
        }

        #pragma unroll
        for (int c = 0; c < 8; c++) {
            int k0 = c * 16 + tg * 2;
            uint2 bh[8], bl[8];
            #pragma unroll
            for (int nt = 0; nt < 8; nt++) {
                int idx = ((c * 16 + wn * 8 + nt) << 5) + lane;
                bh[nt] = g_WfH[idx];
                bl[nt] = g_WfL[idx];
            }
            uint32_t ah[2][4], al[2][4];
            #pragma unroll
            for (int mt = 0; mt < 2; mt++) {
                float2 x00 = v1[mt] ? *(const float2*)(x + (size_t)m1g[mt] * DIM + k0)     : make_float2(0.f, 0.f);
                float2 x10 = v2[mt] ? *(const float2*)(x + (size_t)m2g[mt] * DIM + k0)     : make_float2(0.f, 0.f);
                float2 x01 = v1[mt] ? *(const float2*)(x + (size_t)m1g[mt] * DIM + k0 + 8) : make_float2(0.f, 0.f);
                float2 x11 = v2[mt] ? *(const float2*)(x + (size_t)m2g[mt] * DIM + k0 + 8) : make_float2(0.f, 0.f);
                float r0, r1;
                ah[mt][0] = pkh(x00.x, x00.y, r0, r1); al[mt][0] = pk0(r0, r1);
                ah[mt][1] = pkh(x10.x, x10.y, r0, r1); al[mt][1] = pk0(r0, r1);
                ah[mt][2] = pkh(x01.x, x01.y, r0, r1); al[mt][2] = pk0(r0, r1);
                ah[mt][3] = pkh(x11.x, x11.y, r0, r1); al[mt][3] = pk0(r0, r1);
            }
            #pragma unroll
            for (int nt = 0; nt < 8; nt++) {
                #pragma unroll
                for (int mt = 0; mt < 2; mt++) {
                    float* cc = acc[mt][nt];
                    mma16816bf(cc[0], cc[1], cc[2], cc[3],
                               ah[mt][0], ah[mt][1], ah[mt][2], ah[mt][3],
                               bh[nt].x, bh[nt].y);
                    mma16816bf(cc[0], cc[1], cc[2], cc[3],
                               ah[mt][0], ah[mt][1], ah[mt][2], ah[mt][3],
                               bl[nt].x, bl[nt].y);
                    mma16816bf(cc[0], cc[1], cc[2], cc[3],
                               al[mt][0], al[mt][1], al[mt][2], al[mt][3],
                               bh[nt].x, bh[nt].y);
                }
            }
        }

        #pragma unroll
        for (int mt = 0; mt < 2; mt++) {
            #pragma unroll
            for (int nt = 0; nt < 8; nt++) {
                int col = wn * 64 + nt * 8 + 2 * tg;
                float* cc = acc[mt][nt];
                if (v1[mt])
                    *(float2*)(g_y + (size_t)m1g[mt] * DIM + col) = make_float2(cc[0], cc[1]);
                if (v2[mt])
                    *(float2*)(g_y + (size_t)m2g[mt] * DIM + col) = make_float2(cc[2], cc[3]);
            }
        }
    } else {
        // ---------------- edge block ----------------
        int b = bid;
        int chunk = (E + EB - 1) / EB;
        int beg = b * chunk;
        int end = beg + chunk; if (end > E) end = E;
        if (beg >= end) return;

        __shared__ int s_is64;
        if (threadIdx.x == 0) s_is64 = 1;
        __syncthreads();
        const long long* p64 = (const long long*)ei;
        const int*       p32 = (const int*)ei;
        int samp = end - beg; if (samp > 256) samp = 256;
        if ((int)threadIdx.x < samp) {
            long long v = p64[beg + threadIdx.x];
            if (v < 0 || v >= (long long)N_NODES) s_is64 = 0;
        }
        __syncthreads();
        int is64 = s_is64;

        for (int i = beg + threadIdx.x; i < end; i += 256) {
            int s, t;
            float w = ew[i];
            if (is64) { s = (int)p64[i]; t = (int)p64[(size_t)E + i]; }
            else      { s = p32[i];      t = p32[(size_t)E + i]; }
            atomicAdd(&g_deg[s], w);
            int pos = atomicAdd(&g_cnt[t], 1);
            if (pos < CAP) {
                g_ebuck[(size_t)t * CAP + pos] = make_int2(s, __float_as_int(w));
            } else {
                int o = atomicAdd(&g_ovcnt, 1);
                if (o < OVMAX) { g_ovt[o] = t; g_ovsw[o] = make_int2(s, __float_as_int(w)); }
            }
        }
    }
}

// ---------------- dinv = rsqrt(deg + 1); reset deg; latch overflow --------
__global__ void k_dinv(int n) {
    int i = blockIdx.x * blockDim.x + threadIdx.x;
    if (i < n) {
        g_dinv[i] = rsqrtf(g_deg[i] + 1.0f);
        g_deg[i] = 0.0f;
    }
    if (i == 0) {
        int c = g_ovcnt;
        g_ovuse = (c < OVMAX) ? c : OVMAX;
        g_ovcnt = 0;
    }
}

// ---------------- pull-aggregation: warp per node (exact R14 form) --------
__global__ __launch_bounds__(256) void k_aggregate(const float* __restrict__ bias,
                                                   float* __restrict__ out, int n) {
    __shared__ float2 s_meta[8][CAP];
    int wip  = threadIdx.x >> 5;
    int warp = (blockIdx.x * blockDim.x + threadIdx.x) >> 5;
    int lane = threadIdx.x & 31;
    if (warp >= n) return;
    int t = warp;

    int cnt = g_cnt[t];
    if (cnt > CAP) cnt = CAP;
    const float4* y4 = (const float4*)g_y;
    const int2* buck = g_ebuck + (size_t)t * CAP;
    float di = g_dinv[t];

    // preload + normalize metadata (coalesced; one dinv gather per edge-lane)
    for (int p = lane; p < cnt; p += 32) {
        int2 e = buck[p];
        float wn = __int_as_float(e.y) * g_dinv[e.x] * di;
        s_meta[wip][p] = make_float2(__int_as_float(e.x), wn);
    }
    __syncwarp();

    float sc = di * di;
    float4 self = y4[(size_t)t * 32 + lane];
    float4 bi = ((const float4*)bias)[lane];
    float4 acc0, acc1;
    acc0.x = self.x * sc + bi.x;
    acc0.y = self.y * sc + bi.y;
    acc0.z = self.z * sc + bi.z;
    acc0.w = self.w * sc + bi.w;
    acc1 = make_float4(0.f, 0.f, 0.f, 0.f);

    int j = 0;
    for (; j + 4 <= cnt; j += 4) {
        float2 m0 = s_meta[wip][j];
        float2 m1 = s_meta[wip][j + 1];
        float2 m2 = s_meta[wip][j + 2];
        float2 m3 = s_meta[wip][j + 3];
        float4 v0 = y4[(size_t)__float_as_int(m0.x) * 32 + lane];
        float4 v1 = y4[(size_t)__float_as_int(m1.x) * 32 + lane];
        float4 v2 = y4[(size_t)__float_as_int(m2.x) * 32 + lane];
        float4 v3 = y4[(size_t)__float_as_int(m3.x) * 32 + lane];
        acc0.x += v0.x * m0.y; acc0.y += v0.y * m0.y; acc0.z += v0.z * m0.y; acc0.w += v0.w * m0.y;
        acc1.x += v1.x * m1.y; acc1.y += v1.y * m1.y; acc1.z += v1.z * m1.y; acc1.w += v1.w * m1.y;
        acc0.x += v2.x * m2.y; acc0.y += v2.y * m2.y; acc0.z += v2.z * m2.y; acc0.w += v2.w * m2.y;
        acc1.x += v3.x * m3.y; acc1.y += v3.y * m3.y; acc1.z += v3.z * m3.y; acc1.w += v3.w * m3.y;
    }
    for (; j < cnt; j++) {
        float2 m = s_meta[wip][j];
        float4 v = y4[(size_t)__float_as_int(m.x) * 32 + lane];
        acc0.x += v.x * m.y; acc0.y += v.y * m.y; acc0.z += v.z * m.y; acc0.w += v.w * m.y;
    }

    // overflow tail (normally empty)
    int ov = g_ovuse;
    for (int i = 0; i < ov; i++) {
        if (g_ovt[i] == t) {
            int2 e = g_ovsw[i];
            float wn = __int_as_float(e.y) * g_dinv[e.x] * di;
            float4 v = y4[(size_t)e.x * 32 + lane];
            acc0.x += v.x * wn; acc0.y += v.y * wn; acc0.z += v.z * wn; acc0.w += v.w * wn;
        }
    }

    float4 res;
    res.x = acc0.x + acc1.x;
    res.y = acc0.y + acc1.y;
    res.z = acc0.z + acc1.z;
    res.w = acc0.w + acc1.w;
    ((float4*)out)[(size_t)t * 32 + lane] = res;
    if (lane == 0) g_cnt[t] = 0;
}

extern "C" void kernel_launch(void* const* d_in, const int* in_sizes, int n_in,
                              void* d_out, int out_size) {
    const float* x  = (const float*)d_in[0];
    const void*  ei = d_in[1];
    const float* ew = (const float*)d_in[2];
    const float* W  = (const float*)d_in[3];
    const float* b  = (const float*)d_in[4];
    float* out = (float*)d_out;

    int N = in_sizes[0] / DIM;
    int E = in_sizes[1] / 2;

    int GB = (N + 127) / 128;       // 391 GEMM tiles
    int EB = 592 - GB;              // edge blocks -> grid = exactly 2 waves
    if (EB < 1) EB = 1;

    k_prepW<<<16, 256>>>(W);
    k_fused<<<GB + EB, 256>>>(x, ei, ew, N, E, GB, EB);
    k_dinv<<<(N + 255) / 256, 256>>>(N);
    k_aggregate<<<(N * 32 + 255) / 256, 256>>>(b, out, N);
}